// round 5
// baseline (speedup 1.0000x reference)
#include <cuda_runtime.h>

#define EMBED     128
#define MAXN      200
#define NTHREADS  256
#define LN_EPS    1e-5f

// Pre-transposed weights (scratch; __device__ globals are allowed, no allocation)
__device__ float g_WtT[EMBED * EMBED];
__device__ float g_WhT[EMBED * EMBED];

__global__ void transpose_w(const float* __restrict__ Wt, const float* __restrict__ Wh) {
    int i = blockIdx.x * blockDim.x + threadIdx.x;
    if (i < EMBED * EMBED) {
        int d = i >> 7;        // row of original W
        int e = i & 127;       // col of original W
        g_WtT[e * EMBED + d] = Wt[i];
        g_WhT[e * EMBED + d] = Wh[i];
    }
}

__global__ __launch_bounds__(NTHREADS)
void encoder_kernel(const int*   __restrict__ entity,
                    const int*   __restrict__ conn_left,
                    const int*   __restrict__ conn_right,
                    const float* __restrict__ emb,
                    const float* __restrict__ W_bil,
                    const float* __restrict__ gamma,
                    const float* __restrict__ beta,
                    float*       __restrict__ out,
                    int batch, int pad_idx)
{
    const int b    = blockIdx.x;
    const int side = blockIdx.y;          // 0 = left, 1 = right
    const int tid  = threadIdx.x;
    const int lane = tid & 31;
    const int wid  = tid >> 5;

    __shared__ float s_weak[EMBED];
    __shared__ float s_head[EMBED];
    __shared__ float s_q[EMBED];
    __shared__ float s_sc[MAXN];
    __shared__ int   s_rel[MAXN];
    __shared__ int   s_tail[MAXN];
    __shared__ float s_agg[2][EMBED];
    __shared__ float s_red[8];
    __shared__ float s_red2[8];
    __shared__ float s_bcast[2];

    const int* conn = (side == 0 ? conn_left : conn_right) + (long)b * MAXN * 2;

    // ---- Stage 0: heads, weak_rel, neighbor indices ----
    if (tid < EMBED) {
        int e0 = entity[2 * b];
        int e1 = entity[2 * b + 1];
        float hl = emb[(long)e0 * EMBED + tid];
        float hr = emb[(long)e1 * EMBED + tid];
        s_weak[tid] = hr - hl;
        s_head[tid] = (side == 0) ? hl : hr;
    }
    if (tid < MAXN) {
        s_rel[tid]  = conn[2 * tid];
        s_tail[tid] = conn[2 * tid + 1];
    }
    __syncthreads();

    // ---- Stage 1: q[e] = sum_d weak[d] * W_bil[d,e]  (coalesced over e) ----
    if (tid < EMBED) {
        float acc = 0.f;
        #pragma unroll 8
        for (int d = 0; d < EMBED; d++)
            acc = fmaf(s_weak[d], W_bil[d * EMBED + tid], acc);
        s_q[tid] = acc;
    }
    __syncthreads();

    // ---- Stage 2: scores. One warp per neighbor (strided). ----
    for (int m = wid; m < MAXN; m += 8) {
        int rid = s_rel[m];
        const float4* r  = reinterpret_cast<const float4*>(emb + (long)rid * EMBED);
        float4 v  = r[lane];
        float4 qv = reinterpret_cast<const float4*>(s_q)[lane];
        float p = v.x * qv.x + v.y * qv.y + v.z * qv.z + v.w * qv.w;
        #pragma unroll
        for (int o = 16; o; o >>= 1) p += __shfl_xor_sync(0xffffffffu, p, o);
        if (lane == 0) s_sc[m] = (rid == pad_idx) ? -1e30f : p;
    }
    __syncthreads();

    // ---- Stage 3: softmax (max, exp, sum; normalization folded in later) ----
    {
        float lm = -1e30f;
        for (int m = tid; m < MAXN; m += NTHREADS) lm = fmaxf(lm, s_sc[m]);
        #pragma unroll
        for (int o = 16; o; o >>= 1) lm = fmaxf(lm, __shfl_xor_sync(0xffffffffu, lm, o));
        if (lane == 0) s_red[wid] = lm;
        __syncthreads();
        if (wid == 0) {
            float mv = s_red[lane & 7];
            #pragma unroll
            for (int o = 4; o; o >>= 1) mv = fmaxf(mv, __shfl_xor_sync(0xffffffffu, mv, o));
            if (lane == 0) s_bcast[0] = mv;
        }
        __syncthreads();
        float mx = s_bcast[0];
        float ls = 0.f;
        for (int m = tid; m < MAXN; m += NTHREADS) {
            float e = __expf(s_sc[m] - mx);
            s_sc[m] = e;                       // unnormalized attention
            ls += e;
        }
        #pragma unroll
        for (int o = 16; o; o >>= 1) ls += __shfl_xor_sync(0xffffffffu, ls, o);
        if (lane == 0) s_red2[wid] = ls;
        __syncthreads();
        if (wid == 0) {
            float sv = s_red2[lane & 7];
            #pragma unroll
            for (int o = 4; o; o >>= 1) sv += __shfl_xor_sync(0xffffffffu, sv, o);
            if (lane == 0) s_bcast[1] = 1.f / sv;
        }
        __syncthreads();
    }

    // ---- Stage 4: agg[d] = sum_m att[m] * emb[tail[m]][d] (unnormalized) ----
    {
        int g = tid >> 7;            // half-block split over m
        int d = tid & 127;
        float a0 = 0.f, a1 = 0.f, a2 = 0.f, a3 = 0.f;
        int m0 = g * (MAXN / 2);
        for (int m = m0; m < m0 + MAXN / 2; m += 4) {
            a0 = fmaf(s_sc[m + 0], emb[(long)s_tail[m + 0] * EMBED + d], a0);
            a1 = fmaf(s_sc[m + 1], emb[(long)s_tail[m + 1] * EMBED + d], a1);
            a2 = fmaf(s_sc[m + 2], emb[(long)s_tail[m + 2] * EMBED + d], a2);
            a3 = fmaf(s_sc[m + 3], emb[(long)s_tail[m + 3] * EMBED + d], a3);
        }
        s_agg[g][d] = (a0 + a1) + (a2 + a3);
    }
    __syncthreads();

    const float inv_sum = s_bcast[1];

    // ---- Stage 5: h = relu(agg @ Wt^T + head @ Wh^T); x = h + head ----
    float x = 0.f;
    if (tid < EMBED) {
        int d = tid;
        float acc = 0.f;
        #pragma unroll 4
        for (int e = 0; e < EMBED; e++) {
            float agge = (s_agg[0][e] + s_agg[1][e]) * inv_sum;
            acc = fmaf(agge,      g_WtT[e * EMBED + d], acc);   // coalesced
            acc = fmaf(s_head[e], g_WhT[e * EMBED + d], acc);   // coalesced
        }
        float h = fmaxf(acc, 0.f);
        x = h + s_head[d];
    }

    // ---- Stage 6: LayerNorm over the 128 x-values (upper half contributes 0) ----
    {
        float sx = x, sxx = x * x;
        #pragma unroll
        for (int o = 16; o; o >>= 1) {
            sx  += __shfl_xor_sync(0xffffffffu, sx,  o);
            sxx += __shfl_xor_sync(0xffffffffu, sxx, o);
        }
        if (lane == 0) { s_red[wid] = sx; s_red2[wid] = sxx; }
        __syncthreads();
        float tsum = 0.f, tsq = 0.f;
        #pragma unroll
        for (int w = 0; w < 8; w++) { tsum += s_red[w]; tsq += s_red2[w]; }
        float mu      = tsum * (1.f / EMBED);
        float var     = tsq  * (1.f / EMBED) - mu * mu;
        float inv_std = rsqrtf(var + LN_EPS);
        if (tid < EMBED) {
            float o = (x - mu) * inv_std * gamma[tid] + beta[tid];
            out[((long)side * batch + b) * EMBED + tid] = o;
        }
    }
}

extern "C" void kernel_launch(void* const* d_in, const int* in_sizes, int n_in,
                              void* d_out, int out_size) {
    const int*   entity = (const int*)  d_in[0];
    const int*   cl     = (const int*)  d_in[1];
    const int*   cr     = (const int*)  d_in[2];
    const float* emb    = (const float*)d_in[3];
    const float* W_bil  = (const float*)d_in[4];
    const float* W_tail = (const float*)d_in[5];
    const float* W_head = (const float*)d_in[6];
    const float* gamma  = (const float*)d_in[7];
    const float* beta   = (const float*)d_in[8];
    float* out = (float*)d_out;

    int batch   = in_sizes[0] / 2;             // 1024
    int pad_idx = in_sizes[3] / EMBED - 1;     // 100000

    transpose_w<<<(EMBED * EMBED + 255) / 256, 256>>>(W_tail, W_head);

    dim3 grid(batch, 2);
    encoder_kernel<<<grid, NTHREADS>>>(entity, cl, cr, emb, W_bil,
                                       gamma, beta, out, batch, pad_idx);
}

// round 6
// speedup vs baseline: 1.2300x; 1.2300x over previous
#include <cuda_runtime.h>

#define EMBED     128
#define MAXN      200
#define NTHREADS  256
#define LN_EPS    1e-5f

// Pre-transposed weights (scratch; __device__ globals are allowed, no allocation)
__device__ float g_WtT[EMBED * EMBED];
__device__ float g_WhT[EMBED * EMBED];

__global__ void transpose_w(const float* __restrict__ Wt, const float* __restrict__ Wh) {
    int i = blockIdx.x * blockDim.x + threadIdx.x;
    if (i < EMBED * EMBED) {
        int d = i >> 7;        // row of original W
        int e = i & 127;       // col of original W
        g_WtT[e * EMBED + d] = Wt[i];
        g_WhT[e * EMBED + d] = Wh[i];
    }
}

__global__ __launch_bounds__(NTHREADS)
void encoder_kernel(const int*   __restrict__ entity,
                    const int*   __restrict__ conn_left,
                    const int*   __restrict__ conn_right,
                    const float* __restrict__ emb,
                    const float* __restrict__ W_bil,
                    const float* __restrict__ gamma,
                    const float* __restrict__ beta,
                    float*       __restrict__ out,
                    int batch, int pad_idx)
{
    const int b    = blockIdx.x;
    const int side = blockIdx.y;          // 0 = left, 1 = right
    const int tid  = threadIdx.x;
    const int lane = tid & 31;
    const int wid  = tid >> 5;

    __shared__ float         s_weak[EMBED];
    __shared__ float         s_head[EMBED];
    __shared__ float         s_qp[2 * EMBED];       // split-K partials of q
    __shared__ float         s_sc[MAXN];            // exp(score), unnormalized
    __shared__ const float4* s_rp[MAXN];            // rel row pointers
    __shared__ const float4* s_tp[MAXN];            // tail row pointers
    __shared__ float         s_aggp[8][EMBED];      // per-warp agg partials
    __shared__ float         s_agg[EMBED];          // reduced agg * inv_sum
    __shared__ float         s_part[2][EMBED];      // split-K matvec partials
    __shared__ float         s_red[8];
    __shared__ float         s_red2[8];

    const int* conn = (side == 0 ? conn_left : conn_right) + (long)b * MAXN * 2;

    // ---- Stage 0: heads, weak_rel, neighbor row pointers ----
    if (tid < EMBED) {
        int e0 = entity[2 * b];
        int e1 = entity[2 * b + 1];
        float hl = emb[(size_t)e0 * EMBED + tid];
        float hr = emb[(size_t)e1 * EMBED + tid];
        s_weak[tid] = hr - hl;
        s_head[tid] = (side == 0) ? hl : hr;
    }
    if (tid < MAXN) {
        int2 c = reinterpret_cast<const int2*>(conn)[tid];
        s_rp[tid] = reinterpret_cast<const float4*>(emb + (size_t)c.x * EMBED);
        s_tp[tid] = reinterpret_cast<const float4*>(emb + (size_t)c.y * EMBED);
    }
    __syncthreads();

    // ---- Stage 1: q = weak_rel @ W_bil, split-K over two half-blocks ----
    {
        int half = tid >> 7;
        int e    = tid & 127;
        int d0   = half * 64;
        float acc = 0.f;
        #pragma unroll 8
        for (int d = d0; d < d0 + 64; d++)
            acc = fmaf(s_weak[d], W_bil[d * EMBED + e], acc);
        s_qp[half * EMBED + e] = acc;
    }
    __syncthreads();

    // ---- Stage 2: scores + exp + partial sums (no max-subtraction; scores are tiny) ----
    {
        float4 q0 = reinterpret_cast<const float4*>(s_qp)[lane];
        float4 q1 = reinterpret_cast<const float4*>(s_qp + EMBED)[lane];
        float4 qv = make_float4(q0.x + q1.x, q0.y + q1.y, q0.z + q1.z, q0.w + q1.w);
        const float4* padrow = reinterpret_cast<const float4*>(emb + (size_t)pad_idx * EMBED);

        float lsum = 0.f;
        int m = wid;
        #pragma unroll 4
        for (int it = 0; it < 12; it++, m += 16) {
            const float4* rA = s_rp[m];
            const float4* rB = s_rp[m + 8];
            float4 vA = rA[lane];
            float4 vB = rB[lane];
            float pA = vA.x * qv.x + vA.y * qv.y + vA.z * qv.z + vA.w * qv.w;
            float pB = vB.x * qv.x + vB.y * qv.y + vB.z * qv.z + vB.w * qv.w;
            #pragma unroll
            for (int o = 16; o; o >>= 1) {
                pA += __shfl_xor_sync(0xffffffffu, pA, o);
                pB += __shfl_xor_sync(0xffffffffu, pB, o);
            }
            float eA = (rA == padrow) ? 0.f : __expf(pA);
            float eB = (rB == padrow) ? 0.f : __expf(pB);
            if (lane == 0) { s_sc[m] = eA; s_sc[m + 8] = eB; }
            lsum += eA + eB;
        }
        {   // leftover neighbor: m = wid + 192 (< 200)
            const float4* rA = s_rp[m];
            float4 vA = rA[lane];
            float pA = vA.x * qv.x + vA.y * qv.y + vA.z * qv.z + vA.w * qv.w;
            #pragma unroll
            for (int o = 16; o; o >>= 1) pA += __shfl_xor_sync(0xffffffffu, pA, o);
            float eA = (rA == padrow) ? 0.f : __expf(pA);
            if (lane == 0) s_sc[m] = eA;
            lsum += eA;
        }
        if (lane == 0) s_red[wid] = lsum;
    }
    __syncthreads();

    // ---- Stage 3: aggregation, one warp per neighbor row, float4 ----
    {
        float4 aA = make_float4(0.f, 0.f, 0.f, 0.f);
        float4 aB = make_float4(0.f, 0.f, 0.f, 0.f);
        int m = wid;
        #pragma unroll 4
        for (int it = 0; it < 12; it++, m += 16) {
            const float4* tA = s_tp[m];
            const float4* tB = s_tp[m + 8];
            float attA = s_sc[m];
            float attB = s_sc[m + 8];
            float4 vA = tA[lane];
            float4 vB = tB[lane];
            aA.x = fmaf(attA, vA.x, aA.x);  aA.y = fmaf(attA, vA.y, aA.y);
            aA.z = fmaf(attA, vA.z, aA.z);  aA.w = fmaf(attA, vA.w, aA.w);
            aB.x = fmaf(attB, vB.x, aB.x);  aB.y = fmaf(attB, vB.y, aB.y);
            aB.z = fmaf(attB, vB.z, aB.z);  aB.w = fmaf(attB, vB.w, aB.w);
        }
        {   // leftover: m = wid + 192
            const float4* tA = s_tp[m];
            float attA = s_sc[m];
            float4 vA = tA[lane];
            aA.x = fmaf(attA, vA.x, aA.x);  aA.y = fmaf(attA, vA.y, aA.y);
            aA.z = fmaf(attA, vA.z, aA.z);  aA.w = fmaf(attA, vA.w, aA.w);
        }
        float4 at = make_float4(aA.x + aB.x, aA.y + aB.y, aA.z + aB.z, aA.w + aB.w);
        reinterpret_cast<float4*>(s_aggp[wid])[lane] = at;
    }
    __syncthreads();

    // ---- Stage 4: reduce warp partials, normalize ----
    if (tid < EMBED) {
        float tot = s_red[0] + s_red[1] + s_red[2] + s_red[3]
                  + s_red[4] + s_red[5] + s_red[6] + s_red[7];
        float inv_sum = 1.f / tot;
        float a = 0.f;
        #pragma unroll
        for (int w = 0; w < 8; w++) a += s_aggp[w][tid];
        s_agg[tid] = a * inv_sum;
    }
    __syncthreads();

    // ---- Stage 5: h = relu(agg @ Wt^T + head @ Wh^T), split-K over halves ----
    {
        int half = tid >> 7;
        int d    = tid & 127;
        int e0   = half * 64;
        float acc = 0.f;
        #pragma unroll 4
        for (int e = e0; e < e0 + 64; e++) {
            acc = fmaf(s_agg[e],  g_WtT[e * EMBED + d], acc);
            acc = fmaf(s_head[e], g_WhT[e * EMBED + d], acc);
        }
        s_part[half][d] = acc;
    }
    __syncthreads();

    // ---- Stage 6: residual + LayerNorm (upper half contributes zeros) ----
    float x = 0.f;
    if (tid < EMBED) {
        float h = fmaxf(s_part[0][tid] + s_part[1][tid], 0.f);
        x = h + s_head[tid];
    }
    {
        float sx = x, sxx = x * x;
        #pragma unroll
        for (int o = 16; o; o >>= 1) {
            sx  += __shfl_xor_sync(0xffffffffu, sx,  o);
            sxx += __shfl_xor_sync(0xffffffffu, sxx, o);
        }
        if (lane == 0) { s_red[wid] = sx; s_red2[wid] = sxx; }
        __syncthreads();
        float tsum = 0.f, tsq = 0.f;
        #pragma unroll
        for (int w = 0; w < 8; w++) { tsum += s_red[w]; tsq += s_red2[w]; }
        float mu      = tsum * (1.f / EMBED);
        float var     = tsq  * (1.f / EMBED) - mu * mu;
        float inv_std = rsqrtf(var + LN_EPS);
        if (tid < EMBED) {
            float o = (x - mu) * inv_std * gamma[tid] + beta[tid];
            out[((long)side * batch + b) * EMBED + tid] = o;
        }
    }
}

extern "C" void kernel_launch(void* const* d_in, const int* in_sizes, int n_in,
                              void* d_out, int out_size) {
    const int*   entity = (const int*)  d_in[0];
    const int*   cl     = (const int*)  d_in[1];
    const int*   cr     = (const int*)  d_in[2];
    const float* emb    = (const float*)d_in[3];
    const float* W_bil  = (const float*)d_in[4];
    const float* W_tail = (const float*)d_in[5];
    const float* W_head = (const float*)d_in[6];
    const float* gamma  = (const float*)d_in[7];
    const float* beta   = (const float*)d_in[8];
    float* out = (float*)d_out;

    int batch   = in_sizes[0] / 2;             // 1024
    int pad_idx = in_sizes[3] / EMBED - 1;     // 100000

    transpose_w<<<(EMBED * EMBED + 255) / 256, 256>>>(W_tail, W_head);

    dim3 grid(batch, 2);
    encoder_kernel<<<grid, NTHREADS>>>(entity, cl, cr, emb, W_bil,
                                       gamma, beta, out, batch, pad_idx);
}

// round 7
// speedup vs baseline: 1.2415x; 1.0094x over previous
#include <cuda_runtime.h>

#define EMBED     128
#define MAXN      200
#define NTHREADS  256
#define LN_EPS    1e-5f

// Pre-transposed weights (scratch; __device__ globals are allowed, no allocation)
__device__ float g_WtT[EMBED * EMBED];
__device__ float g_WhT[EMBED * EMBED];

__global__ void transpose_w(const float* __restrict__ Wt, const float* __restrict__ Wh) {
    int i = blockIdx.x * blockDim.x + threadIdx.x;
    if (i < EMBED * EMBED) {
        int d = i >> 7;        // row of original W
        int e = i & 127;       // col of original W
        g_WtT[e * EMBED + d] = Wt[i];
        g_WhT[e * EMBED + d] = Wh[i];
    }
}

// One CTA = one batch element, BOTH sides (left+right share weak_rel/q and all weights).
__global__ __launch_bounds__(NTHREADS)
void encoder_kernel(const int*   __restrict__ entity,
                    const int*   __restrict__ conn_left,
                    const int*   __restrict__ conn_right,
                    const float* __restrict__ emb,
                    const float* __restrict__ W_bil,
                    const float* __restrict__ gamma,
                    const float* __restrict__ beta,
                    float*       __restrict__ out,
                    int batch, int pad_idx)
{
    const int b    = blockIdx.x;
    const int tid  = threadIdx.x;
    const int lane = tid & 31;
    const int wid  = tid >> 5;

    __shared__ float         s_weak[EMBED];
    __shared__ float         s_head[2][EMBED];
    __shared__ float         s_qp[2 * EMBED];        // split-K partials of q
    __shared__ float         s_sc[2][MAXN];          // exp(score), unnormalized
    __shared__ const float4* s_rp[2][MAXN];          // rel row pointers
    __shared__ const float4* s_tp[2][MAXN];          // tail row pointers
    __shared__ float         s_aggp[8][EMBED];       // per-warp agg partials
    __shared__ float         s_agg[2][EMBED];        // reduced agg * inv_sum
    __shared__ float         s_part[2][2][EMBED];    // [half][side][d]
    __shared__ float         s_red[8];
    __shared__ float         s_red2[8];

    // ---- Stage 0: heads, weak_rel, neighbor row pointers for both sides ----
    if (tid < EMBED) {
        int e0 = entity[2 * b];
        int e1 = entity[2 * b + 1];
        float hl = emb[(size_t)e0 * EMBED + tid];
        float hr = emb[(size_t)e1 * EMBED + tid];
        s_weak[tid]    = hr - hl;
        s_head[0][tid] = hl;
        s_head[1][tid] = hr;
    }
    for (int i = tid; i < 2 * MAXN; i += NTHREADS) {
        int s = (i < MAXN) ? 0 : 1;
        int m = (i < MAXN) ? i : i - MAXN;
        const int* conn = (s == 0 ? conn_left : conn_right) + (long)b * MAXN * 2;
        int2 c = reinterpret_cast<const int2*>(conn)[m];
        s_rp[s][m] = reinterpret_cast<const float4*>(emb + (size_t)c.x * EMBED);
        s_tp[s][m] = reinterpret_cast<const float4*>(emb + (size_t)c.y * EMBED);
    }
    __syncthreads();

    // ---- Stage 1: q = weak_rel @ W_bil (shared by both sides), split-K ----
    {
        int half = tid >> 7;
        int e    = tid & 127;
        int d0   = half * 64;
        float acc = 0.f;
        #pragma unroll 8
        for (int d = d0; d < d0 + 64; d++)
            acc = fmaf(s_weak[d], W_bil[d * EMBED + e], acc);
        s_qp[half * EMBED + e] = acc;
    }
    __syncthreads();

    // ---- Stage 2: scores + exp + partial sums. Warps 0-3: side 0, warps 4-7: side 1 ----
    {
        float4 q0 = reinterpret_cast<const float4*>(s_qp)[lane];
        float4 q1 = reinterpret_cast<const float4*>(s_qp + EMBED)[lane];
        float4 qv = make_float4(q0.x + q1.x, q0.y + q1.y, q0.z + q1.z, q0.w + q1.w);
        const float4* padrow = reinterpret_cast<const float4*>(emb + (size_t)pad_idx * EMBED);

        const int s  = wid >> 2;
        const int w4 = wid & 3;
        float lsum = 0.f;
        #pragma unroll 5
        for (int it = 0; it < 25; it++) {
            int m = w4 + it * 8;                  // covers w4 + {0,4,8,...,196}
            const float4* rA = s_rp[s][m];
            const float4* rB = s_rp[s][m + 4];
            float4 vA = rA[lane];
            float4 vB = rB[lane];
            float pA = vA.x * qv.x + vA.y * qv.y + vA.z * qv.z + vA.w * qv.w;
            float pB = vB.x * qv.x + vB.y * qv.y + vB.z * qv.z + vB.w * qv.w;
            #pragma unroll
            for (int o = 16; o; o >>= 1) {
                pA += __shfl_xor_sync(0xffffffffu, pA, o);
                pB += __shfl_xor_sync(0xffffffffu, pB, o);
            }
            float eA = (rA == padrow) ? 0.f : __expf(pA);
            float eB = (rB == padrow) ? 0.f : __expf(pB);
            if (lane == 0) { s_sc[s][m] = eA; s_sc[s][m + 4] = eB; }
            lsum += eA + eB;
        }
        if (lane == 0) s_red[wid] = lsum;
    }
    __syncthreads();

    // ---- Stage 3: aggregation, one warp per row, float4, same warp->side split ----
    {
        const int s  = wid >> 2;
        const int w4 = wid & 3;
        float4 aA = make_float4(0.f, 0.f, 0.f, 0.f);
        float4 aB = make_float4(0.f, 0.f, 0.f, 0.f);
        #pragma unroll 5
        for (int it = 0; it < 25; it++) {
            int m = w4 + it * 8;
            const float4* tA = s_tp[s][m];
            const float4* tB = s_tp[s][m + 4];
            float attA = s_sc[s][m];
            float attB = s_sc[s][m + 4];
            float4 vA = tA[lane];
            float4 vB = tB[lane];
            aA.x = fmaf(attA, vA.x, aA.x);  aA.y = fmaf(attA, vA.y, aA.y);
            aA.z = fmaf(attA, vA.z, aA.z);  aA.w = fmaf(attA, vA.w, aA.w);
            aB.x = fmaf(attB, vB.x, aB.x);  aB.y = fmaf(attB, vB.y, aB.y);
            aB.z = fmaf(attB, vB.z, aB.z);  aB.w = fmaf(attB, vB.w, aB.w);
        }
        float4 at = make_float4(aA.x + aB.x, aA.y + aB.y, aA.z + aB.z, aA.w + aB.w);
        reinterpret_cast<float4*>(s_aggp[wid])[lane] = at;
    }
    __syncthreads();

    // ---- Stage 4: reduce warp partials per side, normalize. 256 threads = 2 sides x 128 ----
    {
        int s = tid >> 7;
        int d = tid & 127;
        float tot = s_red[s * 4] + s_red[s * 4 + 1] + s_red[s * 4 + 2] + s_red[s * 4 + 3];
        float inv_sum = 1.f / tot;
        float a = s_aggp[s * 4][d] + s_aggp[s * 4 + 1][d]
                + s_aggp[s * 4 + 2][d] + s_aggp[s * 4 + 3][d];
        s_agg[s][d] = a * inv_sum;
    }
    __syncthreads();

    // ---- Stage 5: both matvecs share W loads. thread=(half,d); acc for each side ----
    {
        int half = tid >> 7;
        int d    = tid & 127;
        int e0   = half * 64;
        float accL = 0.f, accR = 0.f;
        #pragma unroll 4
        for (int e = e0; e < e0 + 64; e++) {
            float wt = g_WtT[e * EMBED + d];
            float wh = g_WhT[e * EMBED + d];
            accL = fmaf(s_agg[0][e],  wt, accL);
            accL = fmaf(s_head[0][e], wh, accL);
            accR = fmaf(s_agg[1][e],  wt, accR);
            accR = fmaf(s_head[1][e], wh, accR);
        }
        s_part[half][0][d] = accL;
        s_part[half][1][d] = accR;
    }
    __syncthreads();

    // ---- Stage 6: residual + LayerNorm per side. Warps 0-3: side 0, warps 4-7: side 1 ----
    {
        int s = tid >> 7;
        int d = tid & 127;
        float h = fmaxf(s_part[0][s][d] + s_part[1][s][d], 0.f);
        float x = h + s_head[s][d];

        float sx = x, sxx = x * x;
        #pragma unroll
        for (int o = 16; o; o >>= 1) {
            sx  += __shfl_xor_sync(0xffffffffu, sx,  o);
            sxx += __shfl_xor_sync(0xffffffffu, sxx, o);
        }
        if (lane == 0) { s_red[wid] = sx; s_red2[wid] = sxx; }
        __syncthreads();
        float tsum = s_red[s * 4]  + s_red[s * 4 + 1]  + s_red[s * 4 + 2]  + s_red[s * 4 + 3];
        float tsq  = s_red2[s * 4] + s_red2[s * 4 + 1] + s_red2[s * 4 + 2] + s_red2[s * 4 + 3];
        float mu      = tsum * (1.f / EMBED);
        float var     = tsq  * (1.f / EMBED) - mu * mu;
        float inv_std = rsqrtf(var + LN_EPS);
        float o = (x - mu) * inv_std * gamma[d] + beta[d];
        out[((long)s * batch + b) * EMBED + d] = o;
    }
}

extern "C" void kernel_launch(void* const* d_in, const int* in_sizes, int n_in,
                              void* d_out, int out_size) {
    const int*   entity = (const int*)  d_in[0];
    const int*   cl     = (const int*)  d_in[1];
    const int*   cr     = (const int*)  d_in[2];
    const float* emb    = (const float*)d_in[3];
    const float* W_bil  = (const float*)d_in[4];
    const float* W_tail = (const float*)d_in[5];
    const float* W_head = (const float*)d_in[6];
    const float* gamma  = (const float*)d_in[7];
    const float* beta   = (const float*)d_in[8];
    float* out = (float*)d_out;

    int batch   = in_sizes[0] / 2;             // 1024
    int pad_idx = in_sizes[3] / EMBED - 1;     // 100000

    transpose_w<<<(EMBED * EMBED + 255) / 256, 256>>>(W_tail, W_head);

    dim3 grid(batch);
    encoder_kernel<<<grid, NTHREADS>>>(entity, cl, cr, emb, W_bil,
                                       gamma, beta, out, batch, pad_idx);
}

// round 8
// speedup vs baseline: 1.4286x; 1.1507x over previous
#include <cuda_runtime.h>

#define EMBED     128
#define MAXN      200
#define NTHREADS  256
#define LN_EPS    1e-5f

// Pre-transposed weights (scratch; __device__ globals are allowed, no allocation)
__device__ float g_WtT[EMBED * EMBED];
__device__ float g_WhT[EMBED * EMBED];

__global__ void transpose_w(const float* __restrict__ Wt, const float* __restrict__ Wh) {
    int i = blockIdx.x * blockDim.x + threadIdx.x;
    if (i < EMBED * EMBED) {
        int d = i >> 7;
        int e = i & 127;
        g_WtT[e * EMBED + d] = Wt[i];
        g_WhT[e * EMBED + d] = Wh[i];
    }
}

// One CTA = one batch element, BOTH sides. Score + aggregation fully fused.
__global__ __launch_bounds__(NTHREADS)
void encoder_kernel(const int*   __restrict__ entity,
                    const int*   __restrict__ conn_left,
                    const int*   __restrict__ conn_right,
                    const float* __restrict__ emb,
                    const float* __restrict__ W_bil,
                    const float* __restrict__ gamma,
                    const float* __restrict__ beta,
                    float*       __restrict__ out,
                    int batch, int pad_idx)
{
    const int b    = blockIdx.x;
    const int tid  = threadIdx.x;
    const int lane = tid & 31;
    const int wid  = tid >> 5;

    __shared__ float         s_weak[EMBED];
    __shared__ float         s_head[2][EMBED];
    __shared__ float         s_qp[2 * EMBED];
    __shared__ const float4* s_rp[2][MAXN];
    __shared__ const float4* s_tp[2][MAXN];
    __shared__ float         s_aggp[8][EMBED];      // per-warp agg partials
    __shared__ float         s_agg[2][EMBED];
    __shared__ float         s_part[2][2][EMBED];   // [half][side][d]
    __shared__ float         s_red[8];
    __shared__ float         s_red2[8];

    // ---- Stage 0: heads, weak_rel, neighbor row pointers for both sides ----
    if (tid < EMBED) {
        int e0 = entity[2 * b];
        int e1 = entity[2 * b + 1];
        float hl = emb[(size_t)e0 * EMBED + tid];
        float hr = emb[(size_t)e1 * EMBED + tid];
        s_weak[tid]    = hr - hl;
        s_head[0][tid] = hl;
        s_head[1][tid] = hr;
    }
    for (int i = tid; i < 2 * MAXN; i += NTHREADS) {
        int s = (i < MAXN) ? 0 : 1;
        int m = (i < MAXN) ? i : i - MAXN;
        const int* conn = (s == 0 ? conn_left : conn_right) + (long)b * MAXN * 2;
        int2 c = reinterpret_cast<const int2*>(conn)[m];
        s_rp[s][m] = reinterpret_cast<const float4*>(emb + (size_t)c.x * EMBED);
        s_tp[s][m] = reinterpret_cast<const float4*>(emb + (size_t)c.y * EMBED);
    }
    __syncthreads();

    // ---- Stage 1: q = weak_rel @ W_bil (shared by both sides), split-K ----
    {
        int half = tid >> 7;
        int e    = tid & 127;
        int d0   = half * 64;
        float acc = 0.f;
        #pragma unroll 8
        for (int d = d0; d < d0 + 64; d++)
            acc = fmaf(s_weak[d], W_bil[d * EMBED + e], acc);
        s_qp[half * EMBED + e] = acc;
    }
    __syncthreads();

    // ---- Stage 2 (FUSED): score -> exp -> aggregate, 2 rows per iteration ----
    // Warps 0-3: side 0, warps 4-7: side 1. Paired reduction: row A in lanes
    // 0-15, row B in lanes 16-31 (5 shfls for both rows).
    {
        float4 q0 = reinterpret_cast<const float4*>(s_qp)[lane];
        float4 q1 = reinterpret_cast<const float4*>(s_qp + EMBED)[lane];
        float4 qv = make_float4(q0.x + q1.x, q0.y + q1.y, q0.z + q1.z, q0.w + q1.w);
        const float4* padrow = reinterpret_cast<const float4*>(emb + (size_t)pad_idx * EMBED);

        const int s   = wid >> 2;
        const int w4  = wid & 3;
        const bool hi = (lane & 16) != 0;

        float  lsum = 0.f;
        float4 aA = make_float4(0.f, 0.f, 0.f, 0.f);
        float4 aB = make_float4(0.f, 0.f, 0.f, 0.f);

        #pragma unroll 5
        for (int it = 0; it < 25; it++) {
            int m = w4 + it * 8;                 // rows m and m+4; covers all 200
            const float4* rA = s_rp[s][m];
            const float4* rB = s_rp[s][m + 4];
            const float4* tA = s_tp[s][m];
            const float4* tB = s_tp[s][m + 4];
            // issue all 4 gathers up front (tail loads overlap the shfl chain)
            float4 uA = tA[lane];
            float4 uB = tB[lane];
            float4 vA = rA[lane];
            float4 vB = rB[lane];

            float pA = vA.x * qv.x + vA.y * qv.y + vA.z * qv.z + vA.w * qv.w;
            float pB = vB.x * qv.x + vB.y * qv.y + vB.z * qv.z + vB.w * qv.w;

            // paired reduce: lanes 0-15 end with sum(pA), lanes 16-31 with sum(pB)
            float v = hi ? pB : pA;
            float w = hi ? pA : pB;
            v += __shfl_xor_sync(0xffffffffu, w, 16);
            #pragma unroll
            for (int o = 8; o; o >>= 1) v += __shfl_xor_sync(0xffffffffu, v, o);

            bool isPad = hi ? (rB == padrow) : (rA == padrow);
            float e = isPad ? 0.f : __expf(v);
            float attA = __shfl_sync(0xffffffffu, e, 0);
            float attB = __shfl_sync(0xffffffffu, e, 16);
            lsum += attA + attB;

            aA.x = fmaf(attA, uA.x, aA.x);  aA.y = fmaf(attA, uA.y, aA.y);
            aA.z = fmaf(attA, uA.z, aA.z);  aA.w = fmaf(attA, uA.w, aA.w);
            aB.x = fmaf(attB, uB.x, aB.x);  aB.y = fmaf(attB, uB.y, aB.y);
            aB.z = fmaf(attB, uB.z, aB.z);  aB.w = fmaf(attB, uB.w, aB.w);
        }

        float4 at = make_float4(aA.x + aB.x, aA.y + aB.y, aA.z + aB.z, aA.w + aB.w);
        reinterpret_cast<float4*>(s_aggp[wid])[lane] = at;
        if (lane == 0) s_red[wid] = lsum;
    }
    __syncthreads();

    // ---- Stage 3: reduce warp partials per side, normalize ----
    {
        int s = tid >> 7;
        int d = tid & 127;
        float tot = s_red[s * 4] + s_red[s * 4 + 1] + s_red[s * 4 + 2] + s_red[s * 4 + 3];
        float inv_sum = 1.f / tot;
        float a = s_aggp[s * 4][d] + s_aggp[s * 4 + 1][d]
                + s_aggp[s * 4 + 2][d] + s_aggp[s * 4 + 3][d];
        s_agg[s][d] = a * inv_sum;
    }
    __syncthreads();

    // ---- Stage 4: both matvecs share W loads. thread=(half,d), acc per side ----
    {
        int half = tid >> 7;
        int d    = tid & 127;
        int e0   = half * 64;
        float accL = 0.f, accR = 0.f;
        #pragma unroll 4
        for (int e = e0; e < e0 + 64; e++) {
            float wt = g_WtT[e * EMBED + d];
            float wh = g_WhT[e * EMBED + d];
            accL = fmaf(s_agg[0][e],  wt, accL);
            accL = fmaf(s_head[0][e], wh, accL);
            accR = fmaf(s_agg[1][e],  wt, accR);
            accR = fmaf(s_head[1][e], wh, accR);
        }
        s_part[half][0][d] = accL;
        s_part[half][1][d] = accR;
    }
    __syncthreads();

    // ---- Stage 5: residual + LayerNorm per side ----
    {
        int s = tid >> 7;
        int d = tid & 127;
        float h = fmaxf(s_part[0][s][d] + s_part[1][s][d], 0.f);
        float x = h + s_head[s][d];

        float sx = x, sxx = x * x;
        #pragma unroll
        for (int o = 16; o; o >>= 1) {
            sx  += __shfl_xor_sync(0xffffffffu, sx,  o);
            sxx += __shfl_xor_sync(0xffffffffu, sxx, o);
        }
        if (lane == 0) { s_red[wid] = sx; s_red2[wid] = sxx; }
        __syncthreads();
        float tsum = s_red[s * 4]  + s_red[s * 4 + 1]  + s_red[s * 4 + 2]  + s_red[s * 4 + 3];
        float tsq  = s_red2[s * 4] + s_red2[s * 4 + 1] + s_red2[s * 4 + 2] + s_red2[s * 4 + 3];
        float mu      = tsum * (1.f / EMBED);
        float var     = tsq  * (1.f / EMBED) - mu * mu;
        float inv_std = rsqrtf(var + LN_EPS);
        float o = (x - mu) * inv_std * gamma[d] + beta[d];
        out[((long)s * batch + b) * EMBED + d] = o;
    }
}

extern "C" void kernel_launch(void* const* d_in, const int* in_sizes, int n_in,
                              void* d_out, int out_size) {
    const int*   entity = (const int*)  d_in[0];
    const int*   cl     = (const int*)  d_in[1];
    const int*   cr     = (const int*)  d_in[2];
    const float* emb    = (const float*)d_in[3];
    const float* W_bil  = (const float*)d_in[4];
    const float* W_tail = (const float*)d_in[5];
    const float* W_head = (const float*)d_in[6];
    const float* gamma  = (const float*)d_in[7];
    const float* beta   = (const float*)d_in[8];
    float* out = (float*)d_out;

    int batch   = in_sizes[0] / 2;             // 1024
    int pad_idx = in_sizes[3] / EMBED - 1;     // 100000

    transpose_w<<<(EMBED * EMBED + 255) / 256, 256>>>(W_tail, W_head);

    dim3 grid(batch);
    encoder_kernel<<<grid, NTHREADS>>>(entity, cl, cr, emb, W_bil,
                                       gamma, beta, out, batch, pad_idx);
}

// round 11
// speedup vs baseline: 1.5475x; 1.0832x over previous
#include <cuda_runtime.h>

#define EMBED     128
#define MAXN      200
#define NTHREADS  256
#define LN_EPS    1e-5f

// Pre-transposed weights (scratch; __device__ globals are allowed, no allocation)
__device__ float g_WtT[EMBED * EMBED];
__device__ float g_WhT[EMBED * EMBED];

__global__ void transpose_w(const float* __restrict__ Wt, const float* __restrict__ Wh) {
    int i = blockIdx.x * blockDim.x + threadIdx.x;
    if (i < EMBED * EMBED) {
        int d = i >> 7;
        int e = i & 127;
        g_WtT[e * EMBED + d] = Wt[i];
        g_WhT[e * EMBED + d] = Wh[i];
    }
}

// One CTA = one batch element, BOTH sides. Score+exp+aggregate fused, 4 rows/iter.
__global__ __launch_bounds__(NTHREADS, 4)
void encoder_kernel(const int*   __restrict__ entity,
                    const int*   __restrict__ conn_left,
                    const int*   __restrict__ conn_right,
                    const float* __restrict__ emb,
                    const float* __restrict__ W_bil,
                    const float* __restrict__ gamma,
                    const float* __restrict__ beta,
                    float*       __restrict__ out,
                    int batch, int pad_idx)
{
    const int b    = blockIdx.x;
    const int tid  = threadIdx.x;
    const int lane = tid & 31;
    const int wid  = tid >> 5;

    __shared__ float         s_weak[EMBED];
    __shared__ float         s_head[2][EMBED];
    __shared__ float         s_qp[2 * EMBED];
    __shared__ const float4* s_rp[2][MAXN];
    __shared__ const float4* s_tp[2][MAXN];
    __shared__ float         s_aggp[8][EMBED];
    __shared__ float         s_agg[2][EMBED];
    __shared__ float         s_part[2][2][EMBED];
    __shared__ float         s_red[8];
    __shared__ float         s_red2[8];

    // ---- Stage 0: heads, weak_rel, neighbor row pointers for both sides ----
    if (tid < EMBED) {
        int e0 = entity[2 * b];
        int e1 = entity[2 * b + 1];
        float hl = emb[(size_t)e0 * EMBED + tid];
        float hr = emb[(size_t)e1 * EMBED + tid];
        s_weak[tid]    = hr - hl;
        s_head[0][tid] = hl;
        s_head[1][tid] = hr;
    }
    for (int i = tid; i < 2 * MAXN; i += NTHREADS) {
        int s = (i < MAXN) ? 0 : 1;
        int m = (i < MAXN) ? i : i - MAXN;
        const int* conn = (s == 0 ? conn_left : conn_right) + (long)b * MAXN * 2;
        int2 c = reinterpret_cast<const int2*>(conn)[m];
        s_rp[s][m] = reinterpret_cast<const float4*>(emb + (size_t)c.x * EMBED);
        s_tp[s][m] = reinterpret_cast<const float4*>(emb + (size_t)c.y * EMBED);
    }
    __syncthreads();

    // ---- Stage 1: q = weak_rel @ W_bil (shared by both sides), split-K ----
    {
        int half = tid >> 7;
        int e    = tid & 127;
        int d0   = half * 64;
        float acc = 0.f;
        #pragma unroll 8
        for (int d = d0; d < d0 + 64; d++)
            acc = fmaf(s_weak[d], W_bil[d * EMBED + e], acc);
        s_qp[half * EMBED + e] = acc;
    }
    __syncthreads();

    // ---- Stage 2 (FUSED): score -> exp -> aggregate, 4 rows per iteration ----
    // Warps 0-3: side 0, warps 4-7: side 1. Each warp owns 50 contiguous rows.
    {
        float4 q0 = reinterpret_cast<const float4*>(s_qp)[lane];
        float4 q1 = reinterpret_cast<const float4*>(s_qp + EMBED)[lane];
        float4 qv = make_float4(q0.x + q1.x, q0.y + q1.y, q0.z + q1.z, q0.w + q1.w);
        const float4* padrow = reinterpret_cast<const float4*>(emb + (size_t)pad_idx * EMBED);

        const int s    = wid >> 2;
        const int base = (wid & 3) * 50;
        const bool hi16 = (lane & 16) != 0;
        const bool hi8  = (lane & 8)  != 0;

        float  lsum = 0.f;
        float4 a0 = make_float4(0.f,0.f,0.f,0.f);
        float4 a1 = make_float4(0.f,0.f,0.f,0.f);
        float4 a2 = make_float4(0.f,0.f,0.f,0.f);
        float4 a3 = make_float4(0.f,0.f,0.f,0.f);

        #pragma unroll 4
        for (int it = 0; it < 12; it++) {
            int m = base + it * 4;
            const float4* rp0 = s_rp[s][m];
            const float4* rp1 = s_rp[s][m + 1];
            const float4* rp2 = s_rp[s][m + 2];
            const float4* rp3 = s_rp[s][m + 3];
            const float4* tp0 = s_tp[s][m];
            const float4* tp1 = s_tp[s][m + 1];
            const float4* tp2 = s_tp[s][m + 2];
            const float4* tp3 = s_tp[s][m + 3];
            // 8 gathers in flight before any dependent math
            float4 v0 = rp0[lane];
            float4 v1 = rp1[lane];
            float4 v2 = rp2[lane];
            float4 v3 = rp3[lane];
            float4 u0 = tp0[lane];
            float4 u1 = tp1[lane];
            float4 u2 = tp2[lane];
            float4 u3 = tp3[lane];

            float p0 = v0.x*qv.x + v0.y*qv.y + v0.z*qv.z + v0.w*qv.w;
            float p1 = v1.x*qv.x + v1.y*qv.y + v1.z*qv.z + v1.w*qv.w;
            float p2 = v2.x*qv.x + v2.y*qv.y + v2.z*qv.z + v2.w*qv.w;
            float p3 = v3.x*qv.x + v3.y*qv.y + v3.z*qv.z + v3.w*qv.w;

            // 4-row reduce in 5 shfls:
            // pair (p0,p1) across 16-lane halves, pair (p2,p3) likewise,
            // then pair the pairs across 8-lane groups, then reduce 8 lanes.
            float x01 = hi16 ? p1 : p0;
            float y01 = hi16 ? p0 : p1;
            x01 += __shfl_xor_sync(0xffffffffu, y01, 16);
            float x23 = hi16 ? p3 : p2;
            float y23 = hi16 ? p2 : p3;
            x23 += __shfl_xor_sync(0xffffffffu, y23, 16);
            float x = hi8 ? x23 : x01;
            float y = hi8 ? x01 : x23;
            x += __shfl_xor_sync(0xffffffffu, y, 8);
            x += __shfl_xor_sync(0xffffffffu, x, 4);
            x += __shfl_xor_sync(0xffffffffu, x, 2);
            x += __shfl_xor_sync(0xffffffffu, x, 1);
            // lane groups now hold: [0-7]=row0, [8-15]=row2, [16-23]=row1, [24-31]=row3

            const float4* rgA = hi8  ? rp2 : rp0;
            const float4* rgB = hi8  ? rp3 : rp1;
            const float4* rg  = hi16 ? rgB : rgA;
            float e = (rg == padrow) ? 0.f : __expf(x);

            float att0 = __shfl_sync(0xffffffffu, e, 0);
            float att2 = __shfl_sync(0xffffffffu, e, 8);
            float att1 = __shfl_sync(0xffffffffu, e, 16);
            float att3 = __shfl_sync(0xffffffffu, e, 24);
            lsum += (att0 + att1) + (att2 + att3);

            a0.x = fmaf(att0, u0.x, a0.x); a0.y = fmaf(att0, u0.y, a0.y);
            a0.z = fmaf(att0, u0.z, a0.z); a0.w = fmaf(att0, u0.w, a0.w);
            a1.x = fmaf(att1, u1.x, a1.x); a1.y = fmaf(att1, u1.y, a1.y);
            a1.z = fmaf(att1, u1.z, a1.z); a1.w = fmaf(att1, u1.w, a1.w);
            a2.x = fmaf(att2, u2.x, a2.x); a2.y = fmaf(att2, u2.y, a2.y);
            a2.z = fmaf(att2, u2.z, a2.z); a2.w = fmaf(att2, u2.w, a2.w);
            a3.x = fmaf(att3, u3.x, a3.x); a3.y = fmaf(att3, u3.y, a3.y);
            a3.z = fmaf(att3, u3.z, a3.z); a3.w = fmaf(att3, u3.w, a3.w);
        }

        {   // leftover 2 rows: base+48, base+49 (paired 16-lane reduce)
            const float4* rA = s_rp[s][base + 48];
            const float4* rB = s_rp[s][base + 49];
            const float4* tA = s_tp[s][base + 48];
            const float4* tB = s_tp[s][base + 49];
            float4 vA = rA[lane];
            float4 vB = rB[lane];
            float4 uA = tA[lane];
            float4 uB = tB[lane];
            float pA = vA.x*qv.x + vA.y*qv.y + vA.z*qv.z + vA.w*qv.w;
            float pB = vB.x*qv.x + vB.y*qv.y + vB.z*qv.z + vB.w*qv.w;
            float v = hi16 ? pB : pA;
            float w = hi16 ? pA : pB;
            v += __shfl_xor_sync(0xffffffffu, w, 16);
            #pragma unroll
            for (int o = 8; o; o >>= 1) v += __shfl_xor_sync(0xffffffffu, v, o);
            bool isPad = hi16 ? (rB == padrow) : (rA == padrow);
            float e = isPad ? 0.f : __expf(v);
            float attA = __shfl_sync(0xffffffffu, e, 0);
            float attB = __shfl_sync(0xffffffffu, e, 16);
            lsum += attA + attB;
            a0.x = fmaf(attA, uA.x, a0.x); a0.y = fmaf(attA, uA.y, a0.y);
            a0.z = fmaf(attA, uA.z, a0.z); a0.w = fmaf(attA, uA.w, a0.w);
            a1.x = fmaf(attB, uB.x, a1.x); a1.y = fmaf(attB, uB.y, a1.y);
            a1.z = fmaf(attB, uB.z, a1.z); a1.w = fmaf(attB, uB.w, a1.w);
        }

        float4 at = make_float4((a0.x + a1.x) + (a2.x + a3.x),
                                (a0.y + a1.y) + (a2.y + a3.y),
                                (a0.z + a1.z) + (a2.z + a3.z),
                                (a0.w + a1.w) + (a2.w + a3.w));
        reinterpret_cast<float4*>(s_aggp[wid])[lane] = at;
        if (lane == 0) s_red[wid] = lsum;
    }
    __syncthreads();

    // ---- Stage 3: reduce warp partials per side, normalize ----
    {
        int s = tid >> 7;
        int d = tid & 127;
        float tot = s_red[s * 4] + s_red[s * 4 + 1] + s_red[s * 4 + 2] + s_red[s * 4 + 3];
        float inv_sum = 1.f / tot;
        float a = s_aggp[s * 4][d] + s_aggp[s * 4 + 1][d]
                + s_aggp[s * 4 + 2][d] + s_aggp[s * 4 + 3][d];
        s_agg[s][d] = a * inv_sum;
    }
    __syncthreads();

    // ---- Stage 4: both matvecs share W loads. thread=(half,d), acc per side ----
    {
        int half = tid >> 7;
        int d    = tid & 127;
        int e0   = half * 64;
        float accL = 0.f, accR = 0.f;
        #pragma unroll 4
        for (int e = e0; e < e0 + 64; e++) {
            float wt = g_WtT[e * EMBED + d];
            float wh = g_WhT[e * EMBED + d];
            accL = fmaf(s_agg[0][e],  wt, accL);
            accL = fmaf(s_head[0][e], wh, accL);
            accR = fmaf(s_agg[1][e],  wt, accR);
            accR = fmaf(s_head[1][e], wh, accR);
        }
        s_part[half][0][d] = accL;
        s_part[half][1][d] = accR;
    }
    __syncthreads();

    // ---- Stage 5: residual + LayerNorm per side ----
    {
        int s = tid >> 7;
        int d = tid & 127;
        float h = fmaxf(s_part[0][s][d] + s_part[1][s][d], 0.f);
        float x = h + s_head[s][d];

        float sx = x, sxx = x * x;
        #pragma unroll
        for (int o = 16; o; o >>= 1) {
            sx  += __shfl_xor_sync(0xffffffffu, sx,  o);
            sxx += __shfl_xor_sync(0xffffffffu, sxx, o);
        }
        if (lane == 0) { s_red[wid] = sx; s_red2[wid] = sxx; }
        __syncthreads();
        float tsum = s_red[s * 4]  + s_red[s * 4 + 1]  + s_red[s * 4 + 2]  + s_red[s * 4 + 3];
        float tsq  = s_red2[s * 4] + s_red2[s * 4 + 1] + s_red2[s * 4 + 2] + s_red2[s * 4 + 3];
        float mu      = tsum * (1.f / EMBED);
        float var     = tsq  * (1.f / EMBED) - mu * mu;
        float inv_std = rsqrtf(var + LN_EPS);
        float o = (x - mu) * inv_std * gamma[d] + beta[d];
        out[((long)s * batch + b) * EMBED + d] = o;
    }
}

extern "C" void kernel_launch(void* const* d_in, const int* in_sizes, int n_in,
                              void* d_out, int out_size) {
    const int*   entity = (const int*)  d_in[0];
    const int*   cl     = (const int*)  d_in[1];
    const int*   cr     = (const int*)  d_in[2];
    const float* emb    = (const float*)d_in[3];
    const float* W_bil  = (const float*)d_in[4];
    const float* W_tail = (const float*)d_in[5];
    const float* W_head = (const float*)d_in[6];
    const float* gamma  = (const float*)d_in[7];
    const float* beta   = (const float*)d_in[8];
    float* out = (float*)d_out;

    int batch   = in_sizes[0] / 2;             // 1024
    int pad_idx = in_sizes[3] / EMBED - 1;     // 100000

    transpose_w<<<(EMBED * EMBED + 255) / 256, 256>>>(W_tail, W_head);

    dim3 grid(batch);
    encoder_kernel<<<grid, NTHREADS>>>(entity, cl, cr, emb, W_bil,
                                       gamma, beta, out, batch, pad_idx);
}